// round 15
// baseline (speedup 1.0000x reference)
#include <cuda_runtime.h>
#include <cuda_fp16.h>
#include <math.h>
#include <stdint.h>

// ---------------- problem constants ----------------
#define Bq   8
#define Nn   1024
#define Cc   12
#define Ee   256
#define Hh   8
#define Dh   32
#define Ll   4
#define Tt   1025          // N + 1 (cls prepended)
#define XE   1024          // 4*E
#define NCc  5
#define EPSv 1e-5f
#define Mrows (Bq*Tt)      // 8200

// ---------------- scratch (device globals; no allocs) ----------------
__device__ __align__(16) float  g_h [Mrows*Ee];   // residual stream fp32 (carries pos)
__device__ __align__(16) __half g_yh[Mrows*Ee];   // fp16 activations
__device__ __align__(16) __half g_qh[Mrows*Ee];
__device__ __align__(16) __half g_kh[Mrows*Ee];
__device__ __align__(16) __half g_vh[Mrows*Ee];
__device__ __align__(16) __half g_mh[Mrows*XE];   // fp16 MLP hidden
__device__ __align__(16) float  g_pp[4*Bq*Ee];    // pooling partials
// transposed fp16 weights [N][K]
__device__ __align__(16) __half g_wtqkv[3*Ll*Ee*Ee];
__device__ __align__(16) __half g_wto  [Ll*Ee*Ee];
__device__ __align__(16) __half g_wt1  [Ll*XE*Ee];
__device__ __align__(16) __half g_wt2  [Ll*Ee*XE];

// ---------------- small helpers ----------------
__device__ __forceinline__ float gelu_exact(float x) {
    return 0.5f * x * (1.0f + erff(x * 0.70710678118654752f));
}

__device__ __forceinline__ float warpSum(float v) {
#pragma unroll
    for (int off = 16; off > 0; off >>= 1)
        v += __shfl_xor_sync(0xffffffffu, v, off);
    return v;
}

__device__ __forceinline__ float blockSum256(float v, float* red8) {
    int t = threadIdx.x;
    v = warpSum(v);
    if ((t & 31) == 0) red8[t >> 5] = v;
    __syncthreads();
    float r = red8[0];
#pragma unroll
    for (int w = 1; w < 8; ++w) r += red8[w];
    __syncthreads();
    return r;
}

__device__ __forceinline__ uint32_t smem_u32(const void* p) {
    uint32_t a;
    asm("{ .reg .u64 t; cvta.to.shared.u64 t, %1; cvt.u32.u64 %0, t; }" : "=r"(a) : "l"(p));
    return a;
}

__device__ __forceinline__ void ldsm4(uint32_t& r0, uint32_t& r1, uint32_t& r2, uint32_t& r3,
                                      uint32_t addr) {
    asm volatile("ldmatrix.sync.aligned.m8n8.x4.shared.b16 {%0,%1,%2,%3}, [%4];"
                 : "=r"(r0), "=r"(r1), "=r"(r2), "=r"(r3) : "r"(addr));
}

__device__ __forceinline__ void mma16816(float* d, const uint32_t* a, const uint32_t* b) {
    asm volatile(
        "mma.sync.aligned.m16n8k16.row.col.f32.f16.f16.f32 "
        "{%0,%1,%2,%3}, {%4,%5,%6,%7}, {%8,%9}, {%0,%1,%2,%3};"
        : "+f"(d[0]), "+f"(d[1]), "+f"(d[2]), "+f"(d[3])
        : "r"(a[0]), "r"(a[1]), "r"(a[2]), "r"(a[3]), "r"(b[0]), "r"(b[1]));
}

// cp.async helpers (16B, zero-fill when sz==0)
__device__ __forceinline__ void cpasync16(uint32_t dst, const void* src, int sz) {
    asm volatile("cp.async.cg.shared.global [%0], [%1], 16, %2;"
                 :: "r"(dst), "l"(src), "r"(sz) : "memory");
}
__device__ __forceinline__ void cpcommit() {
    asm volatile("cp.async.commit_group;" ::: "memory");
}
template <int N>
__device__ __forceinline__ void cpwait() {
    asm volatile("cp.async.wait_group %0;" :: "n"(N) : "memory");
}

// ---------------- HMMA GEMM: 128x128x32 tile, 8 warps, 3-stage cp.async -------
#define EPI_H16  0   // fp16 out
#define EPI_GELU 1   // fp16 out, gelu
#define EPI_ADD  2   // fp32: h += acc
#define EPI_ADDP 3   // fp32: h += acc + pos  (pre-stage next layer's pos-add)
#define HBM 128
#define HBN 128
#define HBK 32
#define LDA 40
#define LDB 40
#define GSTG 3
#define DSM_G (GSTG * (HBM * LDA + HBN * LDB) * 2)   // 61440 B

template <int EPI>
__device__ __forceinline__ void hgemm_body(
    const __half* __restrict__ A, const __half* __restrict__ Wt,
    const float* __restrict__ bias, const float* __restrict__ res,
    const float* __restrict__ pos,
    float* __restrict__ Cf, __half* __restrict__ Ch,
    char* dsm, int N, int K, int bm, int bn) {
    __half* As = reinterpret_cast<__half*>(dsm);
    __half* Bs = reinterpret_cast<__half*>(dsm + GSTG * HBM * LDA * 2);

    int t = threadIdx.x;
    int w = t >> 5, l = t & 31;
    int wm = (w & 3) * 32, wn = (w >> 2) * 64;

    int arow = t >> 2, ak = (t & 3) * 8;
    int brow = t >> 1, bk16 = (t & 1) * 16;

    uint32_t sA0 = smem_u32(As);
    uint32_t sB0 = smem_u32(Bs);
    const uint32_t bufA = HBM * LDA * 2, bufB = HBN * LDB * 2;
    uint32_t aoff[2], boff[4];
#pragma unroll
    for (int i = 0; i < 2; ++i)
        aoff[i] = ((wm + i * 16 + (l & 15)) * LDA + (l >> 4) * 8) * 2;
#pragma unroll
    for (int p = 0; p < 4; ++p)
        boff[p] = ((wn + p * 16 + (l >> 4) * 8 + (l & 7)) * LDB + ((l >> 3) & 1) * 8) * 2;

    const int szlo = (bm + arow < Mrows) ? 16 : 0;
    const int szhi = (bm + arow + 64 < Mrows) ? 16 : 0;
    const __half* Abase = A + (size_t)(bm + arow) * K + ak;
    const __half* Bbase = Wt + (size_t)(bn + brow) * K + bk16;
    const uint32_t adst0 = (arow * LDA + ak) * 2;
    const uint32_t adst1 = ((arow + 64) * LDA + ak) * 2;
    const uint32_t bdst0 = (brow * LDB + bk16) * 2;
    const uint32_t bdst1 = (brow * LDB + bk16 + 8) * 2;

    float acc[2][8][4];
#pragma unroll
    for (int i = 0; i < 2; ++i)
#pragma unroll
        for (int j = 0; j < 8; ++j)
#pragma unroll
            for (int c = 0; c < 4; ++c) acc[i][j][c] = 0.f;

    const int nk = K / HBK;

    auto issue = [&](int kt) {
        int st = kt % GSTG;
        uint32_t sA = sA0 + st * bufA;
        uint32_t sB = sB0 + st * bufB;
        const __half* ab = Abase + (size_t)kt * HBK;
        const __half* bb = Bbase + (size_t)kt * HBK;
        cpasync16(sA + adst0, ab, szlo);
        cpasync16(sA + adst1, ab + (size_t)64 * K, szhi);
        cpasync16(sB + bdst0, bb, 16);
        cpasync16(sB + bdst1, bb + 8, 16);
        cpcommit();
    };

    issue(0);
    if (nk > 1) issue(1); else cpcommit();
    cpwait<1>();
    __syncthreads();

    for (int kt = 0; kt < nk; ++kt) {
        if (kt + 2 < nk) issue(kt + 2); else cpcommit();

        int st = kt % GSTG;
        uint32_t sA = sA0 + st * bufA;
        uint32_t sB = sB0 + st * bufB;
#pragma unroll
        for (int kk = 0; kk < 2; ++kk) {
            uint32_t a[2][4], b[4][4];
#pragma unroll
            for (int i = 0; i < 2; ++i)
                ldsm4(a[i][0], a[i][1], a[i][2], a[i][3], sA + aoff[i] + kk * 32);
#pragma unroll
            for (int p = 0; p < 4; ++p)
                ldsm4(b[p][0], b[p][1], b[p][2], b[p][3], sB + boff[p] + kk * 32);
#pragma unroll
            for (int i = 0; i < 2; ++i) {
#pragma unroll
                for (int j = 0; j < 8; ++j)
                    mma16816(acc[i][j], a[i], &b[j >> 1][(j & 1) * 2]);
            }
        }
        cpwait<1>();
        __syncthreads();
    }

#pragma unroll
    for (int i = 0; i < 2; ++i) {
        int m0 = bm + wm + i * 16 + (l >> 2);
        int m1 = m0 + 8;
        int tok0 = m0 % Tt, tok1 = m1 % Tt;
#pragma unroll
        for (int j = 0; j < 8; ++j) {
            int n = bn + wn + j * 8 + (l & 3) * 2;
            float bx = bias[n], by = bias[n + 1];
            float v0 = acc[i][j][0] + bx, v1 = acc[i][j][1] + by;
            float v2 = acc[i][j][2] + bx, v3 = acc[i][j][3] + by;
            if (EPI == EPI_ADD || EPI == EPI_ADDP) {
                if (m0 < Mrows) {
                    float2 r0 = *reinterpret_cast<const float2*>(&res[(size_t)m0 * N + n]);
                    v0 += r0.x; v1 += r0.y;
                    if (EPI == EPI_ADDP) {
                        float2 p0 = *reinterpret_cast<const float2*>(&pos[(size_t)tok0 * N + n]);
                        v0 += p0.x; v1 += p0.y;
                    }
                    *reinterpret_cast<float2*>(&Cf[(size_t)m0 * N + n]) = make_float2(v0, v1);
                }
                if (m1 < Mrows) {
                    float2 r1 = *reinterpret_cast<const float2*>(&res[(size_t)m1 * N + n]);
                    v2 += r1.x; v3 += r1.y;
                    if (EPI == EPI_ADDP) {
                        float2 p1 = *reinterpret_cast<const float2*>(&pos[(size_t)tok1 * N + n]);
                        v2 += p1.x; v3 += p1.y;
                    }
                    *reinterpret_cast<float2*>(&Cf[(size_t)m1 * N + n]) = make_float2(v2, v3);
                }
            } else if (EPI == EPI_GELU) {
                if (m0 < Mrows)
                    *reinterpret_cast<__half2*>(&Ch[(size_t)m0 * N + n]) =
                        __floats2half2_rn(gelu_exact(v0), gelu_exact(v1));
                if (m1 < Mrows)
                    *reinterpret_cast<__half2*>(&Ch[(size_t)m1 * N + n]) =
                        __floats2half2_rn(gelu_exact(v2), gelu_exact(v3));
            } else {  // EPI_H16
                if (m0 < Mrows)
                    *reinterpret_cast<__half2*>(&Ch[(size_t)m0 * N + n]) =
                        __floats2half2_rn(v0, v1);
                if (m1 < Mrows)
                    *reinterpret_cast<__half2*>(&Ch[(size_t)m1 * N + n]) =
                        __floats2half2_rn(v2, v3);
            }
        }
    }
}

template <int EPI>
__global__ __launch_bounds__(256, 3) void hgemm(
    const __half* __restrict__ A, const __half* __restrict__ Wt,
    const float* __restrict__ bias, const float* __restrict__ res,
    const float* __restrict__ pos,
    float* __restrict__ Cf, __half* __restrict__ Ch, int N, int K) {
    extern __shared__ __align__(16) char dsm_g[];
    hgemm_body<EPI>(A, Wt, bias, res, pos, Cf, Ch, dsm_g, N, K,
                    blockIdx.y * HBM, blockIdx.x * HBN);
}

__global__ __launch_bounds__(256, 3) void hgemm_qkv(
    const __half* __restrict__ A, const __half* __restrict__ WtL,
    const float* __restrict__ bq, const float* __restrict__ bk, const float* __restrict__ bv,
    __half* __restrict__ q, __half* __restrict__ k, __half* __restrict__ v) {
    extern __shared__ __align__(16) char dsm_g[];
    int z = blockIdx.z;
    const __half* Wt = WtL + (size_t)z * (Ll * Ee * Ee);
    const float* bias = (z == 0) ? bq : (z == 1) ? bk : bv;
    __half* out = (z == 0) ? q : (z == 1) ? k : v;
    hgemm_body<EPI_H16>(A, Wt, bias, nullptr, nullptr, nullptr, out, dsm_g, Ee, Ee,
                        blockIdx.y * HBM, blockIdx.x * HBN);
}

// ---------------- HMMA flash attention v5: i128 x j64, 8 warps, K/V double-buffered
#define LDQ 40
#define LDKf 40
#define LDV 72

__global__ __launch_bounds__(256) void flash5_kernel(
    const __half* __restrict__ qh, const __half* __restrict__ kh,
    const __half* __restrict__ vh, __half* __restrict__ o) {
    __shared__ __align__(16) __half Qs[128 * LDQ];
    __shared__ __align__(16) __half Ks[2][64 * LDKf];
    __shared__ __align__(16) __half Vt[2][32 * LDV];

    int bh = blockIdx.y;
    int b = bh >> 3, h = bh & 7;
    int i0 = blockIdx.x * 128;
    int t = threadIdx.x, w = t >> 5, l = t & 31;

    const __half* qb = qh + (size_t)b * Tt * Ee + h * Dh;
    const __half* kb = kh + (size_t)b * Tt * Ee + h * Dh;
    const __half* vb = vh + (size_t)b * Tt * Ee + h * Dh;

    const uint4 z4 = make_uint4(0, 0, 0, 0);
    const uint2 z2 = make_uint2(0, 0);

    int kjr = t >> 2, kc = (t & 3) * 8;
    int vjp = l * 2, vd0 = w * 4;

    {
        int qr = t >> 1, qc = (t & 1) * 16;
        uint4 v0 = z4, v1 = z4;
        if (i0 + qr < Tt) {
            v0 = *reinterpret_cast<const uint4*>(&qb[(size_t)(i0 + qr) * Ee + qc]);
            v1 = *reinterpret_cast<const uint4*>(&qb[(size_t)(i0 + qr) * Ee + qc + 8]);
        }
        *reinterpret_cast<uint4*>(&Qs[qr * LDQ + qc]) = v0;
        *reinterpret_cast<uint4*>(&Qs[qr * LDQ + qc + 8]) = v1;

        uint4 kv = z4;
        uint2 u0 = z2, u1 = z2;
        if (kjr < Tt)
            kv = *reinterpret_cast<const uint4*>(&kb[(size_t)kjr * Ee + kc]);
        if (vjp < Tt)
            u0 = *reinterpret_cast<const uint2*>(&vb[(size_t)vjp * Ee + vd0]);
        if (vjp + 1 < Tt)
            u1 = *reinterpret_cast<const uint2*>(&vb[(size_t)(vjp + 1) * Ee + vd0]);
        *reinterpret_cast<uint4*>(&Ks[0][kjr * LDKf + kc]) = kv;
        const __half* a0 = reinterpret_cast<const __half*>(&u0);
        const __half* a1 = reinterpret_cast<const __half*>(&u1);
#pragma unroll
        for (int u = 0; u < 4; ++u)
            *reinterpret_cast<__half2*>(&Vt[0][(vd0 + u) * LDV + vjp]) =
                __halves2half2(a0[u], a1[u]);
    }
    __syncthreads();

    uint32_t sQ = smem_u32(Qs), sK0 = smem_u32(&Ks[0][0]), sV0 = smem_u32(&Vt[0][0]);
    const uint32_t bufK = 64 * LDKf * 2, bufV = 32 * LDV * 2;
    uint32_t qoff = ((w * 16 + (l & 15)) * LDQ + (l >> 4) * 8) * 2;
    uint32_t qf[2][4];
    ldsm4(qf[0][0], qf[0][1], qf[0][2], qf[0][3], sQ + qoff);
    ldsm4(qf[1][0], qf[1][1], qf[1][2], qf[1][3], sQ + qoff + 32);

    uint32_t koff[4], voff[2];
#pragma unroll
    for (int p = 0; p < 4; ++p)
        koff[p] = ((p * 16 + (l >> 4) * 8 + (l & 7)) * LDKf + ((l >> 3) & 1) * 8) * 2;
#pragma unroll
    for (int p = 0; p < 2; ++p)
        voff[p] = ((p * 16 + (l >> 4) * 8 + (l & 7)) * LDV + ((l >> 3) & 1) * 8) * 2;

    float of[4][4];
#pragma unroll
    for (int n = 0; n < 4; ++n)
#pragma unroll
        for (int c = 0; c < 4; ++c) of[n][c] = 0.f;
    float lsum0 = 0.f, lsum1 = 0.f;

    const int nIter = (Tt + 63) / 64;   // 17
    for (int it = 0; it < nIter; ++it) {
        int buf = it & 1;
        int j0 = it * 64;
        uint4 kv = z4;
        uint2 u0 = z2, u1 = z2;
        if (it + 1 < nIter) {
            int jn = j0 + 64;
            if (jn + kjr < Tt)
                kv = *reinterpret_cast<const uint4*>(&kb[(size_t)(jn + kjr) * Ee + kc]);
            if (jn + vjp < Tt)
                u0 = *reinterpret_cast<const uint2*>(&vb[(size_t)(jn + vjp) * Ee + vd0]);
            if (jn + vjp + 1 < Tt)
                u1 = *reinterpret_cast<const uint2*>(&vb[(size_t)(jn + vjp + 1) * Ee + vd0]);
        }

        uint32_t sK = sK0 + buf * bufK;
        uint32_t sV = sV0 + buf * bufV;
        float sc[8][4];
#pragma unroll
        for (int j = 0; j < 8; ++j)
#pragma unroll
            for (int c = 0; c < 4; ++c) sc[j][c] = 0.f;
#pragma unroll
        for (int kk = 0; kk < 2; ++kk) {
            uint32_t kbf[4][4];
#pragma unroll
            for (int p = 0; p < 4; ++p)
                ldsm4(kbf[p][0], kbf[p][1], kbf[p][2], kbf[p][3], sK + koff[p] + kk * 32);
#pragma unroll
            for (int j = 0; j < 8; ++j)
                mma16816(sc[j], qf[kk], &kbf[j >> 1][(j & 1) * 2]);
        }
        if (j0 + 64 > Tt) {
#pragma unroll
            for (int j = 0; j < 8; ++j)
#pragma unroll
                for (int c = 0; c < 4; ++c) {
                    int col = j0 + j * 8 + (l & 3) * 2 + (c & 1);
                    if (col >= Tt) sc[j][c] = -1e30f;
                }
        }
        float rs0 = 0.f, rs1 = 0.f;
        uint32_t pa[4][4];
#pragma unroll
        for (int j = 0; j < 8; ++j) {
            float p0 = __expf(sc[j][0]);
            float p1 = __expf(sc[j][1]);
            float p2 = __expf(sc[j][2]);
            float p3 = __expf(sc[j][3]);
            rs0 += p0 + p1;
            rs1 += p2 + p3;
            int kk = j >> 1, hi = (j & 1) * 2;
            __half2 ha = __floats2half2_rn(p0, p1);
            __half2 hb = __floats2half2_rn(p2, p3);
            pa[kk][hi + 0] = *reinterpret_cast<uint32_t*>(&ha);
            pa[kk][hi + 1] = *reinterpret_cast<uint32_t*>(&hb);
        }
        rs0 += __shfl_xor_sync(0xffffffffu, rs0, 1);
        rs0 += __shfl_xor_sync(0xffffffffu, rs0, 2);
        rs1 += __shfl_xor_sync(0xffffffffu, rs1, 1);
        rs1 += __shfl_xor_sync(0xffffffffu, rs1, 2);
        lsum0 += rs0;
        lsum1 += rs1;

#pragma unroll
        for (int kk = 0; kk < 4; ++kk) {
            uint32_t vbf[2][4];
#pragma unroll
            for (int p = 0; p < 2; ++p)
                ldsm4(vbf[p][0], vbf[p][1], vbf[p][2], vbf[p][3], sV + voff[p] + kk * 32);
#pragma unroll
            for (int n = 0; n < 4; ++n)
                mma16816(of[n], pa[kk], &vbf[n >> 1][(n & 1) * 2]);
        }

        if (it + 1 < nIter) {
            int nb = buf ^ 1;
            *reinterpret_cast<uint4*>(&Ks[nb][kjr * LDKf + kc]) = kv;
            const __half* a0 = reinterpret_cast<const __half*>(&u0);
            const __half* a1 = reinterpret_cast<const __half*>(&u1);
#pragma unroll
            for (int u = 0; u < 4; ++u)
                *reinterpret_cast<__half2*>(&Vt[nb][(vd0 + u) * LDV + vjp]) =
                    __halves2half2(a0[u], a1[u]);
            __syncthreads();
        }
    }

    float inv0 = 1.0f / (lsum0 * 16.0f);   // /sqrt(E) AFTER softmax, per reference
    float inv1 = 1.0f / (lsum1 * 16.0f);
    int r0 = i0 + w * 16 + (l >> 2);
    int r1 = r0 + 8;
    size_t rowbase = (size_t)b * Tt;
#pragma unroll
    for (int n = 0; n < 4; ++n) {
        int col = h * Dh + n * 8 + (l & 3) * 2;
        if (r0 < Tt)
            *reinterpret_cast<__half2*>(&o[(rowbase + r0) * Ee + col]) =
                __floats2half2_rn(of[n][0] * inv0, of[n][1] * inv0);
        if (r1 < Tt)
            *reinterpret_cast<__half2*>(&o[(rowbase + r1) * Ee + col]) =
                __floats2half2_rn(of[n][2] * inv1, of[n][3] * inv1);
    }
}

// ---------------- fused weight transpose + fp16 convert (all matrices) --------
__global__ void wconv_all(const float* __restrict__ Wq, const float* __restrict__ Wk,
                          const float* __restrict__ Wv, const float* __restrict__ Wo,
                          const float* __restrict__ W1, const float* __restrict__ W2,
                          __half* __restrict__ wtqkv, __half* __restrict__ wto,
                          __half* __restrict__ wt1,   __half* __restrict__ wt2) {
    __shared__ float tile[32][33];
    int bx = blockIdx.x;
    const float* W;
    __half* Wt;
    int K, N, n0, k0;
    if (bx < 1024) {
        int seg = bx >> 6, tl = bx & 63;
        n0 = (tl & 7) * 32; k0 = (tl >> 3) * 32;
        K = Ee; N = Ee;
        int lyr = seg & 3, m = seg >> 2;
        if (m == 0)      { W = Wq + (size_t)lyr * Ee * Ee; Wt = wtqkv + ((size_t)0 * Ll + lyr) * Ee * Ee; }
        else if (m == 1) { W = Wk + (size_t)lyr * Ee * Ee; Wt = wtqkv + ((size_t)1 * Ll + lyr) * Ee * Ee; }
        else if (m == 2) { W = Wv + (size_t)lyr * Ee * Ee; Wt = wtqkv + ((size_t)2 * Ll + lyr) * Ee * Ee; }
        else             { W = Wo + (size_t)lyr * Ee * Ee; Wt = wto + (size_t)lyr * Ee * Ee; }
    } else if (bx < 2048) {
        int r = bx - 1024;
        int lyr = r >> 8, tl = r & 255;
        n0 = (tl & 31) * 32; k0 = (tl >> 5) * 32;
        K = Ee; N = XE;
        W = W1 + (size_t)lyr * Ee * XE; Wt = wt1 + (size_t)lyr * XE * Ee;
    } else {
        int r = bx - 2048;
        int lyr = r >> 8, tl = r & 255;
        n0 = (tl & 7) * 32; k0 = (tl >> 3) * 32;
        K = XE; N = Ee;
        W = W2 + (size_t)lyr * XE * Ee; Wt = wt2 + (size_t)lyr * Ee * XE;
    }
    int tx = threadIdx.x, ty = threadIdx.y;
#pragma unroll
    for (int i = 0; i < 32; i += 8)
        tile[ty + i][tx] = W[(size_t)(k0 + ty + i) * N + n0 + tx];
    __syncthreads();
#pragma unroll
    for (int i = 0; i < 32; i += 8)
        Wt[(size_t)(n0 + ty + i) * K + k0 + tx] = __float2half(tile[tx][ty + i]);
}

// ---------------- embedding (warp-per-row) + pos (layer 0) + cls rows ---------
__global__ __launch_bounds__(256) void embed_warp_kernel(
    const float* __restrict__ x, const float* __restrict__ W,
    const float* __restrict__ bias, const float* __restrict__ g,
    const float* __restrict__ be, const float* __restrict__ cls,
    const float* __restrict__ pos, float* __restrict__ h) {
    int w = threadIdx.x >> 5, l = threadIdx.x & 31;
    int row = blockIdx.x * 8 + w;
    int e0 = l * 8;
    if (row >= Bq * Nn) {
        // cls block: warp w handles batch w: h[b][0][:] = cls + pos[0]
        int b = w;
        float4 c0 = *reinterpret_cast<const float4*>(&cls[e0]);
        float4 c1 = *reinterpret_cast<const float4*>(&cls[e0 + 4]);
        float4 p0 = *reinterpret_cast<const float4*>(&pos[e0]);
        float4 p1 = *reinterpret_cast<const float4*>(&pos[e0 + 4]);
        float* hr = h + (size_t)b * Tt * Ee + e0;
        *reinterpret_cast<float4*>(hr) =
            make_float4(c0.x + p0.x, c0.y + p0.y, c0.z + p0.z, c0.w + p0.w);
        *reinterpret_cast<float4*>(hr + 4) =
            make_float4(c1.x + p1.x, c1.y + p1.y, c1.z + p1.z, c1.w + p1.w);
        return;
    }
    int b = row >> 10, n = row & 1023;
    const float* xr = x + (size_t)row * Cc;
    float acc[8];
#pragma unroll
    for (int u = 0; u < 8; ++u) acc[u] = bias[e0 + u];
#pragma unroll
    for (int c = 0; c < Cc; ++c) {
        float xv = xr[c];
        const float* wr = W + c * Ee + e0;
        float4 w0 = *reinterpret_cast<const float4*>(wr);
        float4 w1 = *reinterpret_cast<const float4*>(wr + 4);
        acc[0] = fmaf(xv, w0.x, acc[0]); acc[1] = fmaf(xv, w0.y, acc[1]);
        acc[2] = fmaf(xv, w0.z, acc[2]); acc[3] = fmaf(xv, w0.w, acc[3]);
        acc[4] = fmaf(xv, w1.x, acc[4]); acc[5] = fmaf(xv, w1.y, acc[5]);
        acc[6] = fmaf(xv, w1.z, acc[6]); acc[7] = fmaf(xv, w1.w, acc[7]);
    }
    float s = 0.f;
#pragma unroll
    for (int u = 0; u < 8; ++u) s += acc[u];
    float mean = warpSum(s) * (1.0f / Ee);
    float vs = 0.f;
#pragma unroll
    for (int u = 0; u < 8; ++u) { float d = acc[u] - mean; vs += d * d; }
    float rstd = rsqrtf(warpSum(vs) * (1.0f / Ee) + EPSv);
    float4 g0 = *reinterpret_cast<const float4*>(&g[e0]);
    float4 g1 = *reinterpret_cast<const float4*>(&g[e0 + 4]);
    float4 b0 = *reinterpret_cast<const float4*>(&be[e0]);
    float4 b1 = *reinterpret_cast<const float4*>(&be[e0 + 4]);
    float gv[8] = {g0.x, g0.y, g0.z, g0.w, g1.x, g1.y, g1.z, g1.w};
    float bv[8] = {b0.x, b0.y, b0.z, b0.w, b1.x, b1.y, b1.z, b1.w};
    const float* pr = pos + (size_t)(n + 1) * Ee + e0;
    float4 p0 = *reinterpret_cast<const float4*>(pr);
    float4 p1 = *reinterpret_cast<const float4*>(pr + 4);
    float pv[8] = {p0.x, p0.y, p0.z, p0.w, p1.x, p1.y, p1.z, p1.w};
    float out[8];
#pragma unroll
    for (int u = 0; u < 8; ++u)
        out[u] = gelu_exact((acc[u] - mean) * rstd * gv[u] + bv[u]) + pv[u];
    float* hr = h + ((size_t)b * Tt + (n + 1)) * Ee + e0;
    *reinterpret_cast<float4*>(hr)     = make_float4(out[0], out[1], out[2], out[3]);
    *reinterpret_cast<float4*>(hr + 4) = make_float4(out[4], out[5], out[6], out[7]);
}

// warp-per-row pure LN: y = fp16(LN(h))
__global__ __launch_bounds__(256) void ln_warp_kernel(
    const float* __restrict__ h,
    const float* __restrict__ g, const float* __restrict__ bb,
    __half* __restrict__ y) {
    int w = threadIdx.x >> 5, l = threadIdx.x & 31;
    int row = blockIdx.x * 8 + w;
    if (row >= Mrows) return;
    int e0 = l * 8;
    const float* hr = h + (size_t)row * Ee + e0;
    float4 h0 = *reinterpret_cast<const float4*>(hr);
    float4 h1 = *reinterpret_cast<const float4*>(hr + 4);
    float v[8] = {h0.x, h0.y, h0.z, h0.w, h1.x, h1.y, h1.z, h1.w};
    float s = 0.f;
#pragma unroll
    for (int u = 0; u < 8; ++u) s += v[u];
    float mean = warpSum(s) * (1.0f / Ee);
    float vs = 0.f;
#pragma unroll
    for (int u = 0; u < 8; ++u) { float d = v[u] - mean; vs += d * d; }
    float rstd = rsqrtf(warpSum(vs) * (1.0f / Ee) + EPSv);
    float4 g0 = *reinterpret_cast<const float4*>(&g[e0]);
    float4 g1 = *reinterpret_cast<const float4*>(&g[e0 + 4]);
    float4 b0 = *reinterpret_cast<const float4*>(&bb[e0]);
    float4 b1 = *reinterpret_cast<const float4*>(&bb[e0 + 4]);
    float gv[8] = {g0.x, g0.y, g0.z, g0.w, g1.x, g1.y, g1.z, g1.w};
    float bv[8] = {b0.x, b0.y, b0.z, b0.w, b1.x, b1.y, b1.z, b1.w};
    __half2 o[4];
#pragma unroll
    for (int u = 0; u < 4; ++u)
        o[u] = __floats2half2_rn((v[2*u]   - mean) * rstd * gv[2*u]   + bv[2*u],
                                 (v[2*u+1] - mean) * rstd * gv[2*u+1] + bv[2*u+1]);
    *reinterpret_cast<uint4*>(y + (size_t)row * Ee + e0) =
        *reinterpret_cast<const uint4*>(o);
}

// ---------------- mean pool (partials) ----------------
__global__ void pool_partial_kernel(const float* __restrict__ h, float* __restrict__ pp) {
    int c = blockIdx.x, b = blockIdx.y, e = threadIdx.x;
    float sum = 0.f;
    for (int t = c; t < Tt; t += 4)
        sum += h[((size_t)b * Tt + t) * Ee + e];
    pp[((size_t)c * Bq + b) * Ee + e] = sum;
}

// ---------------- classifier ----------------
__global__ void classifier_kernel(const float* __restrict__ pp,
                                  const float* __restrict__ Wc1, const float* __restrict__ bc1,
                                  const float* __restrict__ lg, const float* __restrict__ lb,
                                  const float* __restrict__ Wc2, const float* __restrict__ bc2,
                                  float* __restrict__ out) {
    int b = blockIdx.x, e = threadIdx.x;
    __shared__ float pr[Ee];
    __shared__ float u[Ee];
    __shared__ float red8[8];
    float s = 0.f;
#pragma unroll
    for (int c = 0; c < 4; ++c) s += pp[((size_t)c * Bq + b) * Ee + e];
    pr[e] = s * (1.0f / Tt);
    __syncthreads();
    float acc = bc1[e];
    for (int kk = 0; kk < Ee; ++kk) acc = fmaf(pr[kk], Wc1[kk * Ee + e], acc);
    float mean = blockSum256(acc, red8) * (1.0f / Ee);
    float d = acc - mean;
    float var = blockSum256(d * d, red8) * (1.0f / Ee);
    u[e] = d * rsqrtf(var + EPSv) * lg[e] + lb[e];
    __syncthreads();
    if (e < NCc) {
        float o = bc2[e];
        for (int kk = 0; kk < Ee; ++kk) o = fmaf(u[kk], Wc2[kk * NCc + e], o);
        out[b * NCc + e] = o;
    }
}

// ---------------- launch ----------------
extern "C" void kernel_launch(void* const* d_in, const int* in_sizes, int n_in,
                              void* d_out, int out_size) {
    const float* x        = (const float*)d_in[0];
    const float* W_emb    = (const float*)d_in[1];
    const float* b_emb    = (const float*)d_in[2];
    const float* g_emb    = (const float*)d_in[3];
    const float* be_emb   = (const float*)d_in[4];
    const float* cls_tok  = (const float*)d_in[5];
    const float* pos      = (const float*)d_in[6];
    const float* ln1_g    = (const float*)d_in[7];
    const float* ln1_b    = (const float*)d_in[8];
    const float* Wq       = (const float*)d_in[9];
    const float* bq       = (const float*)d_in[10];
    const float* Wk       = (const float*)d_in[11];
    const float* bk       = (const float*)d_in[12];
    const float* Wv       = (const float*)d_in[13];
    const float* bv       = (const float*)d_in[14];
    const float* Wo       = (const float*)d_in[15];
    const float* bo       = (const float*)d_in[16];
    const float* ln2_g    = (const float*)d_in[17];
    const float* ln2_b    = (const float*)d_in[18];
    const float* W1       = (const float*)d_in[19];
    const float* b1       = (const float*)d_in[20];
    const float* W2       = (const float*)d_in[21];
    const float* b2       = (const float*)d_in[22];
    const float* Wc1      = (const float*)d_in[23];
    const float* bc1      = (const float*)d_in[24];
    const float* lnc_g    = (const float*)d_in[25];
    const float* lnc_b    = (const float*)d_in[26];
    const float* Wc2      = (const float*)d_in[27];
    const float* bc2      = (const float*)d_in[28];

    float *h, *pp;
    __half *yh, *qh, *kh, *vh, *mh, *wtqkv, *wto, *wt1, *wt2;
    cudaGetSymbolAddress((void**)&h,     g_h);
    cudaGetSymbolAddress((void**)&yh,    g_yh);
    cudaGetSymbolAddress((void**)&qh,    g_qh);
    cudaGetSymbolAddress((void**)&kh,    g_kh);
    cudaGetSymbolAddress((void**)&vh,    g_vh);
    cudaGetSymbolAddress((void**)&mh,    g_mh);
    cudaGetSymbolAddress((void**)&pp,    g_pp);
    cudaGetSymbolAddress((void**)&wtqkv, g_wtqkv);
    cudaGetSymbolAddress((void**)&wto,   g_wto);
    cudaGetSymbolAddress((void**)&wt1,   g_wt1);
    cudaGetSymbolAddress((void**)&wt2,   g_wt2);

    cudaFuncSetAttribute(hgemm<EPI_GELU>, cudaFuncAttributeMaxDynamicSharedMemorySize, DSM_G);
    cudaFuncSetAttribute(hgemm<EPI_ADD>,  cudaFuncAttributeMaxDynamicSharedMemorySize, DSM_G);
    cudaFuncSetAttribute(hgemm<EPI_ADDP>, cudaFuncAttributeMaxDynamicSharedMemorySize, DSM_G);
    cudaFuncSetAttribute(hgemm_qkv,       cudaFuncAttributeMaxDynamicSharedMemorySize, DSM_G);

    // weight prep (single fused launch)
    wconv_all<<<3072, dim3(32, 8)>>>(Wq, Wk, Wv, Wo, W1, W2, wtqkv, wto, wt1, wt2);

    // embed (+layer-0 pos) + cls rows, single launch (grid +1 block for cls)
    embed_warp_kernel<<<(Bq * Nn) / 8 + 1, 256>>>(x, W_emb, b_emb, g_emb, be_emb,
                                                  cls_tok, pos, h);

    const int M = Mrows;
    const int mt = (M + HBM - 1) / HBM;               // 65
    const int lnGrid = (M + 7) / 8;                   // 1025
    dim3 gQKV(Ee / HBN, mt, 3);                       // (2, 65, 3)
    dim3 g256(Ee / HBN, mt);                          // (2, 65)
    dim3 g1024(XE / HBN, mt);                         // (8, 65)
    dim3 fgrid((Tt + 127) / 128, Bq * Hh);            // (9, 64)

    for (int l = 0; l < Ll; ++l) {
        // h already carries this layer's pos (embed for l=0, W2 epilogue otherwise)
        ln_warp_kernel<<<lnGrid, 256>>>(h, ln1_g + l * Ee, ln1_b + l * Ee, yh);

        hgemm_qkv<<<gQKV, 256, DSM_G>>>(yh, wtqkv + (size_t)l * Ee * Ee,
                                        bq + l * Ee, bk + l * Ee, bv + l * Ee, qh, kh, vh);

        flash5_kernel<<<fgrid, 256>>>(qh, kh, vh, yh);

        hgemm<EPI_ADD><<<g256, 256, DSM_G>>>(yh, wto + (size_t)l * Ee * Ee,
                                             bo + l * Ee, h, nullptr, h, nullptr, Ee, Ee);

        ln_warp_kernel<<<lnGrid, 256>>>(h, ln2_g + l * Ee, ln2_b + l * Ee, yh);

        hgemm<EPI_GELU><<<g1024, 256, DSM_G>>>(yh, wt1 + (size_t)l * XE * Ee,
                                               b1 + l * XE, nullptr, nullptr,
                                               nullptr, mh, XE, Ee);

        if (l + 1 < Ll) {
            hgemm<EPI_ADDP><<<g256, 256, DSM_G>>>(mh, wt2 + (size_t)l * Ee * XE,
                                                  b2 + l * Ee, h, pos, h, nullptr, Ee, XE);
        } else {
            hgemm<EPI_ADD><<<g256, 256, DSM_G>>>(mh, wt2 + (size_t)l * Ee * XE,
                                                 b2 + l * Ee, h, nullptr, h, nullptr, Ee, XE);
        }
    }

    dim3 pgrid(4, Bq);
    pool_partial_kernel<<<pgrid, 256>>>(h, pp);
    classifier_kernel<<<Bq, 256>>>(pp, Wc1, bc1, lnc_g, lnc_b, Wc2, bc2, (float*)d_out);
}

// round 16
// speedup vs baseline: 1.3219x; 1.3219x over previous
#include <cuda_runtime.h>
#include <cuda_fp16.h>
#include <math.h>
#include <stdint.h>

// ---------------- problem constants ----------------
#define Bq   8
#define Nn   1024
#define Cc   12
#define Ee   256
#define Hh   8
#define Dh   32
#define Ll   4
#define Tt   1025          // N + 1 (cls prepended)
#define XE   1024          // 4*E
#define NCc  5
#define EPSv 1e-5f
#define Mrows (Bq*Tt)      // 8200

// ---------------- scratch (device globals; no allocs) ----------------
__device__ __align__(16) float  g_h [Mrows*Ee];   // residual stream fp32 (carries pos)
__device__ __align__(16) __half g_yh[Mrows*Ee];   // fp16 activations
__device__ __align__(16) __half g_qh[Mrows*Ee];
__device__ __align__(16) __half g_kh[Mrows*Ee];
__device__ __align__(16) __half g_vh[Mrows*Ee];
__device__ __align__(16) __half g_mh[Mrows*XE];   // fp16 MLP hidden
__device__ __align__(16) float  g_pp[4*Bq*Ee];    // pooling partials
// transposed fp16 weights [N][K]
__device__ __align__(16) __half g_wtqkv[3*Ll*Ee*Ee];
__device__ __align__(16) __half g_wto  [Ll*Ee*Ee];
__device__ __align__(16) __half g_wt1  [Ll*XE*Ee];
__device__ __align__(16) __half g_wt2  [Ll*Ee*XE];

// ---------------- small helpers ----------------
__device__ __forceinline__ float gelu_exact(float x) {
    return 0.5f * x * (1.0f + erff(x * 0.70710678118654752f));
}

__device__ __forceinline__ float warpSum(float v) {
#pragma unroll
    for (int off = 16; off > 0; off >>= 1)
        v += __shfl_xor_sync(0xffffffffu, v, off);
    return v;
}

__device__ __forceinline__ float blockSum256(float v, float* red8) {
    int t = threadIdx.x;
    v = warpSum(v);
    if ((t & 31) == 0) red8[t >> 5] = v;
    __syncthreads();
    float r = red8[0];
#pragma unroll
    for (int w = 1; w < 8; ++w) r += red8[w];
    __syncthreads();
    return r;
}

__device__ __forceinline__ uint32_t smem_u32(const void* p) {
    uint32_t a;
    asm("{ .reg .u64 t; cvta.to.shared.u64 t, %1; cvt.u32.u64 %0, t; }" : "=r"(a) : "l"(p));
    return a;
}

__device__ __forceinline__ void ldsm4(uint32_t& r0, uint32_t& r1, uint32_t& r2, uint32_t& r3,
                                      uint32_t addr) {
    asm volatile("ldmatrix.sync.aligned.m8n8.x4.shared.b16 {%0,%1,%2,%3}, [%4];"
                 : "=r"(r0), "=r"(r1), "=r"(r2), "=r"(r3) : "r"(addr));
}

__device__ __forceinline__ void mma16816(float* d, const uint32_t* a, const uint32_t* b) {
    asm volatile(
        "mma.sync.aligned.m16n8k16.row.col.f32.f16.f16.f32 "
        "{%0,%1,%2,%3}, {%4,%5,%6,%7}, {%8,%9}, {%0,%1,%2,%3};"
        : "+f"(d[0]), "+f"(d[1]), "+f"(d[2]), "+f"(d[3])
        : "r"(a[0]), "r"(a[1]), "r"(a[2]), "r"(a[3]), "r"(b[0]), "r"(b[1]));
}

// cp.async helpers (16B, zero-fill when sz==0)
__device__ __forceinline__ void cpasync16(uint32_t dst, const void* src, int sz) {
    asm volatile("cp.async.cg.shared.global [%0], [%1], 16, %2;"
                 :: "r"(dst), "l"(src), "r"(sz) : "memory");
}
__device__ __forceinline__ void cpcommit() {
    asm volatile("cp.async.commit_group;" ::: "memory");
}
template <int N>
__device__ __forceinline__ void cpwait() {
    asm volatile("cp.async.wait_group %0;" :: "n"(N) : "memory");
}

// ---------------- HMMA GEMM: 128x128x32 tile, 8 warps, 4-stage cp.async -------
#define EPI_H16  0   // fp16 out
#define EPI_GELU 1   // fp16 out, gelu
#define EPI_ADD  2   // fp32: h += acc
#define EPI_ADDP 3   // fp32: h += acc + pos  (pre-stage next layer's pos-add)
#define HBM 128
#define HBN 128
#define HBK 32
#define LDA 40
#define LDB 40
#define GSTG 4
#define DSM_G (GSTG * (HBM * LDA + HBN * LDB) * 2)   // 81920 B

template <int EPI>
__device__ __forceinline__ void hgemm_body(
    const __half* __restrict__ A, const __half* __restrict__ Wt,
    const float* __restrict__ bias, const float* __restrict__ res,
    const float* __restrict__ pos,
    float* __restrict__ Cf, __half* __restrict__ Ch,
    char* dsm, int N, int K, int bm, int bn) {
    __half* As = reinterpret_cast<__half*>(dsm);
    __half* Bs = reinterpret_cast<__half*>(dsm + GSTG * HBM * LDA * 2);

    int t = threadIdx.x;
    int w = t >> 5, l = t & 31;
    int wm = (w & 3) * 32, wn = (w >> 2) * 64;

    int arow = t >> 2, ak = (t & 3) * 8;
    int brow = t >> 1, bk16 = (t & 1) * 16;

    uint32_t sA0 = smem_u32(As);
    uint32_t sB0 = smem_u32(Bs);
    const uint32_t bufA = HBM * LDA * 2, bufB = HBN * LDB * 2;
    uint32_t aoff[2], boff[4];
#pragma unroll
    for (int i = 0; i < 2; ++i)
        aoff[i] = ((wm + i * 16 + (l & 15)) * LDA + (l >> 4) * 8) * 2;
#pragma unroll
    for (int p = 0; p < 4; ++p)
        boff[p] = ((wn + p * 16 + (l >> 4) * 8 + (l & 7)) * LDB + ((l >> 3) & 1) * 8) * 2;

    const int szlo = (bm + arow < Mrows) ? 16 : 0;
    const int szhi = (bm + arow + 64 < Mrows) ? 16 : 0;
    const __half* Abase = A + (size_t)(bm + arow) * K + ak;
    const __half* Bbase = Wt + (size_t)(bn + brow) * K + bk16;
    const uint32_t adst0 = (arow * LDA + ak) * 2;
    const uint32_t adst1 = ((arow + 64) * LDA + ak) * 2;
    const uint32_t bdst0 = (brow * LDB + bk16) * 2;
    const uint32_t bdst1 = (brow * LDB + bk16 + 8) * 2;

    float acc[2][8][4];
#pragma unroll
    for (int i = 0; i < 2; ++i)
#pragma unroll
        for (int j = 0; j < 8; ++j)
#pragma unroll
            for (int c = 0; c < 4; ++c) acc[i][j][c] = 0.f;

    const int nk = K / HBK;

    auto issue = [&](int kt) {
        if (kt < nk) {
            int st = kt % GSTG;
            uint32_t sA = sA0 + st * bufA;
            uint32_t sB = sB0 + st * bufB;
            const __half* ab = Abase + (size_t)kt * HBK;
            const __half* bb = Bbase + (size_t)kt * HBK;
            cpasync16(sA + adst0, ab, szlo);
            cpasync16(sA + adst1, ab + (size_t)64 * K, szhi);
            cpasync16(sB + bdst0, bb, 16);
            cpasync16(sB + bdst1, bb + 8, 16);
        }
        cpcommit();
    };

    issue(0);
    issue(1);
    issue(2);
    cpwait<2>();       // stage 0 complete
    __syncthreads();

    for (int kt = 0; kt < nk; ++kt) {
        issue(kt + 3);

        int st = kt % GSTG;
        uint32_t sA = sA0 + st * bufA;
        uint32_t sB = sB0 + st * bufB;
#pragma unroll
        for (int kk = 0; kk < 2; ++kk) {
            uint32_t a[2][4], b[4][4];
#pragma unroll
            for (int i = 0; i < 2; ++i)
                ldsm4(a[i][0], a[i][1], a[i][2], a[i][3], sA + aoff[i] + kk * 32);
#pragma unroll
            for (int p = 0; p < 4; ++p)
                ldsm4(b[p][0], b[p][1], b[p][2], b[p][3], sB + boff[p] + kk * 32);
#pragma unroll
            for (int i = 0; i < 2; ++i) {
#pragma unroll
                for (int j = 0; j < 8; ++j)
                    mma16816(acc[i][j], a[i], &b[j >> 1][(j & 1) * 2]);
            }
        }
        cpwait<2>();       // group kt+1 complete (pending: kt+2, kt+3)
        __syncthreads();   // cross-thread visibility + buffer-reuse safety
    }

#pragma unroll
    for (int i = 0; i < 2; ++i) {
        int m0 = bm + wm + i * 16 + (l >> 2);
        int m1 = m0 + 8;
        int tok0 = m0 % Tt, tok1 = m1 % Tt;
#pragma unroll
        for (int j = 0; j < 8; ++j) {
            int n = bn + wn + j * 8 + (l & 3) * 2;
            float bx = bias[n], by = bias[n + 1];
            float v0 = acc[i][j][0] + bx, v1 = acc[i][j][1] + by;
            float v2 = acc[i][j][2] + bx, v3 = acc[i][j][3] + by;
            if (EPI == EPI_ADD || EPI == EPI_ADDP) {
                if (m0 < Mrows) {
                    float2 r0 = *reinterpret_cast<const float2*>(&res[(size_t)m0 * N + n]);
                    v0 += r0.x; v1 += r0.y;
                    if (EPI == EPI_ADDP) {
                        float2 p0 = *reinterpret_cast<const float2*>(&pos[(size_t)tok0 * N + n]);
                        v0 += p0.x; v1 += p0.y;
                    }
                    *reinterpret_cast<float2*>(&Cf[(size_t)m0 * N + n]) = make_float2(v0, v1);
                }
                if (m1 < Mrows) {
                    float2 r1 = *reinterpret_cast<const float2*>(&res[(size_t)m1 * N + n]);
                    v2 += r1.x; v3 += r1.y;
                    if (EPI == EPI_ADDP) {
                        float2 p1 = *reinterpret_cast<const float2*>(&pos[(size_t)tok1 * N + n]);
                        v2 += p1.x; v3 += p1.y;
                    }
                    *reinterpret_cast<float2*>(&Cf[(size_t)m1 * N + n]) = make_float2(v2, v3);
                }
            } else if (EPI == EPI_GELU) {
                if (m0 < Mrows)
                    *reinterpret_cast<__half2*>(&Ch[(size_t)m0 * N + n]) =
                        __floats2half2_rn(gelu_exact(v0), gelu_exact(v1));
                if (m1 < Mrows)
                    *reinterpret_cast<__half2*>(&Ch[(size_t)m1 * N + n]) =
                        __floats2half2_rn(gelu_exact(v2), gelu_exact(v3));
            } else {  // EPI_H16
                if (m0 < Mrows)
                    *reinterpret_cast<__half2*>(&Ch[(size_t)m0 * N + n]) =
                        __floats2half2_rn(v0, v1);
                if (m1 < Mrows)
                    *reinterpret_cast<__half2*>(&Ch[(size_t)m1 * N + n]) =
                        __floats2half2_rn(v2, v3);
            }
        }
    }
}

template <int EPI>
__global__ __launch_bounds__(256) void hgemm(
    const __half* __restrict__ A, const __half* __restrict__ Wt,
    const float* __restrict__ bias, const float* __restrict__ res,
    const float* __restrict__ pos,
    float* __restrict__ Cf, __half* __restrict__ Ch, int N, int K) {
    extern __shared__ __align__(16) char dsm_g[];
    hgemm_body<EPI>(A, Wt, bias, res, pos, Cf, Ch, dsm_g, N, K,
                    blockIdx.y * HBM, blockIdx.x * HBN);
}

__global__ __launch_bounds__(256) void hgemm_qkv(
    const __half* __restrict__ A, const __half* __restrict__ WtL,
    const float* __restrict__ bq, const float* __restrict__ bk, const float* __restrict__ bv,
    __half* __restrict__ q, __half* __restrict__ k, __half* __restrict__ v) {
    extern __shared__ __align__(16) char dsm_g[];
    int z = blockIdx.z;
    const __half* Wt = WtL + (size_t)z * (Ll * Ee * Ee);
    const float* bias = (z == 0) ? bq : (z == 1) ? bk : bv;
    __half* out = (z == 0) ? q : (z == 1) ? k : v;
    hgemm_body<EPI_H16>(A, Wt, bias, nullptr, nullptr, nullptr, out, dsm_g, Ee, Ee,
                        blockIdx.y * HBM, blockIdx.x * HBN);
}

// ---------------- HMMA flash attention v5: i128 x j64, 8 warps, K/V double-buffered
#define LDQ 40
#define LDKf 40
#define LDV 72

__global__ __launch_bounds__(256) void flash5_kernel(
    const __half* __restrict__ qh, const __half* __restrict__ kh,
    const __half* __restrict__ vh, __half* __restrict__ o) {
    __shared__ __align__(16) __half Qs[128 * LDQ];
    __shared__ __align__(16) __half Ks[2][64 * LDKf];
    __shared__ __align__(16) __half Vt[2][32 * LDV];

    int bh = blockIdx.y;
    int b = bh >> 3, h = bh & 7;
    int i0 = blockIdx.x * 128;
    int t = threadIdx.x, w = t >> 5, l = t & 31;

    const __half* qb = qh + (size_t)b * Tt * Ee + h * Dh;
    const __half* kb = kh + (size_t)b * Tt * Ee + h * Dh;
    const __half* vb = vh + (size_t)b * Tt * Ee + h * Dh;

    const uint4 z4 = make_uint4(0, 0, 0, 0);
    const uint2 z2 = make_uint2(0, 0);

    int kjr = t >> 2, kc = (t & 3) * 8;
    int vjp = l * 2, vd0 = w * 4;

    {
        int qr = t >> 1, qc = (t & 1) * 16;
        uint4 v0 = z4, v1 = z4;
        if (i0 + qr < Tt) {
            v0 = *reinterpret_cast<const uint4*>(&qb[(size_t)(i0 + qr) * Ee + qc]);
            v1 = *reinterpret_cast<const uint4*>(&qb[(size_t)(i0 + qr) * Ee + qc + 8]);
        }
        *reinterpret_cast<uint4*>(&Qs[qr * LDQ + qc]) = v0;
        *reinterpret_cast<uint4*>(&Qs[qr * LDQ + qc + 8]) = v1;

        uint4 kv = z4;
        uint2 u0 = z2, u1 = z2;
        if (kjr < Tt)
            kv = *reinterpret_cast<const uint4*>(&kb[(size_t)kjr * Ee + kc]);
        if (vjp < Tt)
            u0 = *reinterpret_cast<const uint2*>(&vb[(size_t)vjp * Ee + vd0]);
        if (vjp + 1 < Tt)
            u1 = *reinterpret_cast<const uint2*>(&vb[(size_t)(vjp + 1) * Ee + vd0]);
        *reinterpret_cast<uint4*>(&Ks[0][kjr * LDKf + kc]) = kv;
        const __half* a0 = reinterpret_cast<const __half*>(&u0);
        const __half* a1 = reinterpret_cast<const __half*>(&u1);
#pragma unroll
        for (int u = 0; u < 4; ++u)
            *reinterpret_cast<__half2*>(&Vt[0][(vd0 + u) * LDV + vjp]) =
                __halves2half2(a0[u], a1[u]);
    }
    __syncthreads();

    uint32_t sQ = smem_u32(Qs), sK0 = smem_u32(&Ks[0][0]), sV0 = smem_u32(&Vt[0][0]);
    const uint32_t bufK = 64 * LDKf * 2, bufV = 32 * LDV * 2;
    uint32_t qoff = ((w * 16 + (l & 15)) * LDQ + (l >> 4) * 8) * 2;
    uint32_t qf[2][4];
    ldsm4(qf[0][0], qf[0][1], qf[0][2], qf[0][3], sQ + qoff);
    ldsm4(qf[1][0], qf[1][1], qf[1][2], qf[1][3], sQ + qoff + 32);

    uint32_t koff[4], voff[2];
#pragma unroll
    for (int p = 0; p < 4; ++p)
        koff[p] = ((p * 16 + (l >> 4) * 8 + (l & 7)) * LDKf + ((l >> 3) & 1) * 8) * 2;
#pragma unroll
    for (int p = 0; p < 2; ++p)
        voff[p] = ((p * 16 + (l >> 4) * 8 + (l & 7)) * LDV + ((l >> 3) & 1) * 8) * 2;

    float of[4][4];
#pragma unroll
    for (int n = 0; n < 4; ++n)
#pragma unroll
        for (int c = 0; c < 4; ++c) of[n][c] = 0.f;
    float lsum0 = 0.f, lsum1 = 0.f;

    const int nIter = (Tt + 63) / 64;   // 17
    for (int it = 0; it < nIter; ++it) {
        int buf = it & 1;
        int j0 = it * 64;
        uint4 kv = z4;
        uint2 u0 = z2, u1 = z2;
        if (it + 1 < nIter) {
            int jn = j0 + 64;
            if (jn + kjr < Tt)
                kv = *reinterpret_cast<const uint4*>(&kb[(size_t)(jn + kjr) * Ee + kc]);
            if (jn + vjp < Tt)
                u0 = *reinterpret_cast<const uint2*>(&vb[(size_t)(jn + vjp) * Ee + vd0]);
            if (jn + vjp + 1 < Tt)
                u1 = *reinterpret_cast<const uint2*>(&vb[(size_t)(jn + vjp + 1) * Ee + vd0]);
        }

        uint32_t sK = sK0 + buf * bufK;
        uint32_t sV = sV0 + buf * bufV;
        float sc[8][4];
#pragma unroll
        for (int j = 0; j < 8; ++j)
#pragma unroll
            for (int c = 0; c < 4; ++c) sc[j][c] = 0.f;
#pragma unroll
        for (int kk = 0; kk < 2; ++kk) {
            uint32_t kbf[4][4];
#pragma unroll
            for (int p = 0; p < 4; ++p)
                ldsm4(kbf[p][0], kbf[p][1], kbf[p][2], kbf[p][3], sK + koff[p] + kk * 32);
#pragma unroll
            for (int j = 0; j < 8; ++j)
                mma16816(sc[j], qf[kk], &kbf[j >> 1][(j & 1) * 2]);
        }
        if (j0 + 64 > Tt) {
#pragma unroll
            for (int j = 0; j < 8; ++j)
#pragma unroll
                for (int c = 0; c < 4; ++c) {
                    int col = j0 + j * 8 + (l & 3) * 2 + (c & 1);
                    if (col >= Tt) sc[j][c] = -1e30f;
                }
        }
        float rs0 = 0.f, rs1 = 0.f;
        uint32_t pa[4][4];
#pragma unroll
        for (int j = 0; j < 8; ++j) {
            float p0 = __expf(sc[j][0]);
            float p1 = __expf(sc[j][1]);
            float p2 = __expf(sc[j][2]);
            float p3 = __expf(sc[j][3]);
            rs0 += p0 + p1;
            rs1 += p2 + p3;
            int kk = j >> 1, hi = (j & 1) * 2;
            __half2 ha = __floats2half2_rn(p0, p1);
            __half2 hb = __floats2half2_rn(p2, p3);
            pa[kk][hi + 0] = *reinterpret_cast<uint32_t*>(&ha);
            pa[kk][hi + 1] = *reinterpret_cast<uint32_t*>(&hb);
        }
        rs0 += __shfl_xor_sync(0xffffffffu, rs0, 1);
        rs0 += __shfl_xor_sync(0xffffffffu, rs0, 2);
        rs1 += __shfl_xor_sync(0xffffffffu, rs1, 1);
        rs1 += __shfl_xor_sync(0xffffffffu, rs1, 2);
        lsum0 += rs0;
        lsum1 += rs1;

#pragma unroll
        for (int kk = 0; kk < 4; ++kk) {
            uint32_t vbf[2][4];
#pragma unroll
            for (int p = 0; p < 2; ++p)
                ldsm4(vbf[p][0], vbf[p][1], vbf[p][2], vbf[p][3], sV + voff[p] + kk * 32);
#pragma unroll
            for (int n = 0; n < 4; ++n)
                mma16816(of[n], pa[kk], &vbf[n >> 1][(n & 1) * 2]);
        }

        if (it + 1 < nIter) {
            int nb = buf ^ 1;
            *reinterpret_cast<uint4*>(&Ks[nb][kjr * LDKf + kc]) = kv;
            const __half* a0 = reinterpret_cast<const __half*>(&u0);
            const __half* a1 = reinterpret_cast<const __half*>(&u1);
#pragma unroll
            for (int u = 0; u < 4; ++u)
                *reinterpret_cast<__half2*>(&Vt[nb][(vd0 + u) * LDV + vjp]) =
                    __halves2half2(a0[u], a1[u]);
            __syncthreads();
        }
    }

    float inv0 = 1.0f / (lsum0 * 16.0f);   // /sqrt(E) AFTER softmax, per reference
    float inv1 = 1.0f / (lsum1 * 16.0f);
    int r0 = i0 + w * 16 + (l >> 2);
    int r1 = r0 + 8;
    size_t rowbase = (size_t)b * Tt;
#pragma unroll
    for (int n = 0; n < 4; ++n) {
        int col = h * Dh + n * 8 + (l & 3) * 2;
        if (r0 < Tt)
            *reinterpret_cast<__half2*>(&o[(rowbase + r0) * Ee + col]) =
                __floats2half2_rn(of[n][0] * inv0, of[n][1] * inv0);
        if (r1 < Tt)
            *reinterpret_cast<__half2*>(&o[(rowbase + r1) * Ee + col]) =
                __floats2half2_rn(of[n][2] * inv1, of[n][3] * inv1);
    }
}

// ---------------- fused weight transpose + fp16 convert (all matrices) --------
__global__ void wconv_all(const float* __restrict__ Wq, const float* __restrict__ Wk,
                          const float* __restrict__ Wv, const float* __restrict__ Wo,
                          const float* __restrict__ W1, const float* __restrict__ W2,
                          __half* __restrict__ wtqkv, __half* __restrict__ wto,
                          __half* __restrict__ wt1,   __half* __restrict__ wt2) {
    __shared__ float tile[32][33];
    int bx = blockIdx.x;
    const float* W;
    __half* Wt;
    int K, N, n0, k0;
    if (bx < 1024) {
        int seg = bx >> 6, tl = bx & 63;
        n0 = (tl & 7) * 32; k0 = (tl >> 3) * 32;
        K = Ee; N = Ee;
        int lyr = seg & 3, m = seg >> 2;
        if (m == 0)      { W = Wq + (size_t)lyr * Ee * Ee; Wt = wtqkv + ((size_t)0 * Ll + lyr) * Ee * Ee; }
        else if (m == 1) { W = Wk + (size_t)lyr * Ee * Ee; Wt = wtqkv + ((size_t)1 * Ll + lyr) * Ee * Ee; }
        else if (m == 2) { W = Wv + (size_t)lyr * Ee * Ee; Wt = wtqkv + ((size_t)2 * Ll + lyr) * Ee * Ee; }
        else             { W = Wo + (size_t)lyr * Ee * Ee; Wt = wto + (size_t)lyr * Ee * Ee; }
    } else if (bx < 2048) {
        int r = bx - 1024;
        int lyr = r >> 8, tl = r & 255;
        n0 = (tl & 31) * 32; k0 = (tl >> 5) * 32;
        K = Ee; N = XE;
        W = W1 + (size_t)lyr * Ee * XE; Wt = wt1 + (size_t)lyr * XE * Ee;
    } else {
        int r = bx - 2048;
        int lyr = r >> 8, tl = r & 255;
        n0 = (tl & 7) * 32; k0 = (tl >> 3) * 32;
        K = XE; N = Ee;
        W = W2 + (size_t)lyr * XE * Ee; Wt = wt2 + (size_t)lyr * Ee * XE;
    }
    int tx = threadIdx.x, ty = threadIdx.y;
#pragma unroll
    for (int i = 0; i < 32; i += 8)
        tile[ty + i][tx] = W[(size_t)(k0 + ty + i) * N + n0 + tx];
    __syncthreads();
#pragma unroll
    for (int i = 0; i < 32; i += 8)
        Wt[(size_t)(n0 + ty + i) * K + k0 + tx] = __float2half(tile[tx][ty + i]);
}

// ---------------- embedding (warp-per-row) + pos (layer 0) + cls rows ---------
__global__ __launch_bounds__(256) void embed_warp_kernel(
    const float* __restrict__ x, const float* __restrict__ W,
    const float* __restrict__ bias, const float* __restrict__ g,
    const float* __restrict__ be, const float* __restrict__ cls,
    const float* __restrict__ pos, float* __restrict__ h) {
    int w = threadIdx.x >> 5, l = threadIdx.x & 31;
    int row = blockIdx.x * 8 + w;
    int e0 = l * 8;
    if (row >= Bq * Nn) {
        int b = w;
        float4 c0 = *reinterpret_cast<const float4*>(&cls[e0]);
        float4 c1 = *reinterpret_cast<const float4*>(&cls[e0 + 4]);
        float4 p0 = *reinterpret_cast<const float4*>(&pos[e0]);
        float4 p1 = *reinterpret_cast<const float4*>(&pos[e0 + 4]);
        float* hr = h + (size_t)b * Tt * Ee + e0;
        *reinterpret_cast<float4*>(hr) =
            make_float4(c0.x + p0.x, c0.y + p0.y, c0.z + p0.z, c0.w + p0.w);
        *reinterpret_cast<float4*>(hr + 4) =
            make_float4(c1.x + p1.x, c1.y + p1.y, c1.z + p1.z, c1.w + p1.w);
        return;
    }
    int b = row >> 10, n = row & 1023;
    const float* xr = x + (size_t)row * Cc;
    float acc[8];
#pragma unroll
    for (int u = 0; u < 8; ++u) acc[u] = bias[e0 + u];
#pragma unroll
    for (int c = 0; c < Cc; ++c) {
        float xv = xr[c];
        const float* wr = W + c * Ee + e0;
        float4 w0 = *reinterpret_cast<const float4*>(wr);
        float4 w1 = *reinterpret_cast<const float4*>(wr + 4);
        acc[0] = fmaf(xv, w0.x, acc[0]); acc[1] = fmaf(xv, w0.y, acc[1]);
        acc[2] = fmaf(xv, w0.z, acc[2]); acc[3] = fmaf(xv, w0.w, acc[3]);
        acc[4] = fmaf(xv, w1.x, acc[4]); acc[5] = fmaf(xv, w1.y, acc[5]);
        acc[6] = fmaf(xv, w1.z, acc[6]); acc[7] = fmaf(xv, w1.w, acc[7]);
    }
    float s = 0.f;
#pragma unroll
    for (int u = 0; u < 8; ++u) s += acc[u];
    float mean = warpSum(s) * (1.0f / Ee);
    float vs = 0.f;
#pragma unroll
    for (int u = 0; u < 8; ++u) { float d = acc[u] - mean; vs += d * d; }
    float rstd = rsqrtf(warpSum(vs) * (1.0f / Ee) + EPSv);
    float4 g0 = *reinterpret_cast<const float4*>(&g[e0]);
    float4 g1 = *reinterpret_cast<const float4*>(&g[e0 + 4]);
    float4 b0 = *reinterpret_cast<const float4*>(&be[e0]);
    float4 b1 = *reinterpret_cast<const float4*>(&be[e0 + 4]);
    float gv[8] = {g0.x, g0.y, g0.z, g0.w, g1.x, g1.y, g1.z, g1.w};
    float bv[8] = {b0.x, b0.y, b0.z, b0.w, b1.x, b1.y, b1.z, b1.w};
    const float* pr = pos + (size_t)(n + 1) * Ee + e0;
    float4 p0 = *reinterpret_cast<const float4*>(pr);
    float4 p1 = *reinterpret_cast<const float4*>(pr + 4);
    float pv[8] = {p0.x, p0.y, p0.z, p0.w, p1.x, p1.y, p1.z, p1.w};
    float out[8];
#pragma unroll
    for (int u = 0; u < 8; ++u)
        out[u] = gelu_exact((acc[u] - mean) * rstd * gv[u] + bv[u]) + pv[u];
    float* hr = h + ((size_t)b * Tt + (n + 1)) * Ee + e0;
    *reinterpret_cast<float4*>(hr)     = make_float4(out[0], out[1], out[2], out[3]);
    *reinterpret_cast<float4*>(hr + 4) = make_float4(out[4], out[5], out[6], out[7]);
}

// warp-per-row pure LN: y = fp16(LN(h))
__global__ __launch_bounds__(256) void ln_warp_kernel(
    const float* __restrict__ h,
    const float* __restrict__ g, const float* __restrict__ bb,
    __half* __restrict__ y) {
    int w = threadIdx.x >> 5, l = threadIdx.x & 31;
    int row = blockIdx.x * 8 + w;
    if (row >= Mrows) return;
    int e0 = l * 8;
    const float* hr = h + (size_t)row * Ee + e0;
    float4 h0 = *reinterpret_cast<const float4*>(hr);
    float4 h1 = *reinterpret_cast<const float4*>(hr + 4);
    float v[8] = {h0.x, h0.y, h0.z, h0.w, h1.x, h1.y, h1.z, h1.w};
    float s = 0.f;
#pragma unroll
    for (int u = 0; u < 8; ++u) s += v[u];
    float mean = warpSum(s) * (1.0f / Ee);
    float vs = 0.f;
#pragma unroll
    for (int u = 0; u < 8; ++u) { float d = v[u] - mean; vs += d * d; }
    float rstd = rsqrtf(warpSum(vs) * (1.0f / Ee) + EPSv);
    float4 g0 = *reinterpret_cast<const float4*>(&g[e0]);
    float4 g1 = *reinterpret_cast<const float4*>(&g[e0 + 4]);
    float4 b0 = *reinterpret_cast<const float4*>(&bb[e0]);
    float4 b1 = *reinterpret_cast<const float4*>(&bb[e0 + 4]);
    float gv[8] = {g0.x, g0.y, g0.z, g0.w, g1.x, g1.y, g1.z, g1.w};
    float bv[8] = {b0.x, b0.y, b0.z, b0.w, b1.x, b1.y, b1.z, b1.w};
    __half2 o[4];
#pragma unroll
    for (int u = 0; u < 4; ++u)
        o[u] = __floats2half2_rn((v[2*u]   - mean) * rstd * gv[2*u]   + bv[2*u],
                                 (v[2*u+1] - mean) * rstd * gv[2*u+1] + bv[2*u+1]);
    *reinterpret_cast<uint4*>(y + (size_t)row * Ee + e0) =
        *reinterpret_cast<const uint4*>(o);
}

// ---------------- mean pool (partials) ----------------
__global__ void pool_partial_kernel(const float* __restrict__ h, float* __restrict__ pp) {
    int c = blockIdx.x, b = blockIdx.y, e = threadIdx.x;
    float sum = 0.f;
    for (int t = c; t < Tt; t += 4)
        sum += h[((size_t)b * Tt + t) * Ee + e];
    pp[((size_t)c * Bq + b) * Ee + e] = sum;
}

// ---------------- classifier ----------------
__global__ void classifier_kernel(const float* __restrict__ pp,
                                  const float* __restrict__ Wc1, const float* __restrict__ bc1,
                                  const float* __restrict__ lg, const float* __restrict__ lb,
                                  const float* __restrict__ Wc2, const float* __restrict__ bc2,
                                  float* __restrict__ out) {
    int b = blockIdx.x, e = threadIdx.x;
    __shared__ float pr[Ee];
    __shared__ float u[Ee];
    __shared__ float red8[8];
    float s = 0.f;
#pragma unroll
    for (int c = 0; c < 4; ++c) s += pp[((size_t)c * Bq + b) * Ee + e];
    pr[e] = s * (1.0f / Tt);
    __syncthreads();
    float acc = bc1[e];
    for (int kk = 0; kk < Ee; ++kk) acc = fmaf(pr[kk], Wc1[kk * Ee + e], acc);
    float mean = blockSum256(acc, red8) * (1.0f / Ee);
    float d = acc - mean;
    float var = blockSum256(d * d, red8) * (1.0f / Ee);
    u[e] = d * rsqrtf(var + EPSv) * lg[e] + lb[e];
    __syncthreads();
    if (e < NCc) {
        float o = bc2[e];
        for (int kk = 0; kk < Ee; ++kk) o = fmaf(u[kk], Wc2[kk * NCc + e], o);
        out[b * NCc + e] = o;
    }
}

// ---------------- launch ----------------
extern "C" void kernel_launch(void* const* d_in, const int* in_sizes, int n_in,
                              void* d_out, int out_size) {
    const float* x        = (const float*)d_in[0];
    const float* W_emb    = (const float*)d_in[1];
    const float* b_emb    = (const float*)d_in[2];
    const float* g_emb    = (const float*)d_in[3];
    const float* be_emb   = (const float*)d_in[4];
    const float* cls_tok  = (const float*)d_in[5];
    const float* pos      = (const float*)d_in[6];
    const float* ln1_g    = (const float*)d_in[7];
    const float* ln1_b    = (const float*)d_in[8];
    const float* Wq       = (const float*)d_in[9];
    const float* bq       = (const float*)d_in[10];
    const float* Wk       = (const float*)d_in[11];
    const float* bk       = (const float*)d_in[12];
    const float* Wv       = (const float*)d_in[13];
    const float* bv       = (const float*)d_in[14];
    const float* Wo       = (const float*)d_in[15];
    const float* bo       = (const float*)d_in[16];
    const float* ln2_g    = (const float*)d_in[17];
    const float* ln2_b    = (const float*)d_in[18];
    const float* W1       = (const float*)d_in[19];
    const float* b1       = (const float*)d_in[20];
    const float* W2       = (const float*)d_in[21];
    const float* b2       = (const float*)d_in[22];
    const float* Wc1      = (const float*)d_in[23];
    const float* bc1      = (const float*)d_in[24];
    const float* lnc_g    = (const float*)d_in[25];
    const float* lnc_b    = (const float*)d_in[26];
    const float* Wc2      = (const float*)d_in[27];
    const float* bc2      = (const float*)d_in[28];

    float *h, *pp;
    __half *yh, *qh, *kh, *vh, *mh, *wtqkv, *wto, *wt1, *wt2;
    cudaGetSymbolAddress((void**)&h,     g_h);
    cudaGetSymbolAddress((void**)&yh,    g_yh);
    cudaGetSymbolAddress((void**)&qh,    g_qh);
    cudaGetSymbolAddress((void**)&kh,    g_kh);
    cudaGetSymbolAddress((void**)&vh,    g_vh);
    cudaGetSymbolAddress((void**)&mh,    g_mh);
    cudaGetSymbolAddress((void**)&pp,    g_pp);
    cudaGetSymbolAddress((void**)&wtqkv, g_wtqkv);
    cudaGetSymbolAddress((void**)&wto,   g_wto);
    cudaGetSymbolAddress((void**)&wt1,   g_wt1);
    cudaGetSymbolAddress((void**)&wt2,   g_wt2);

    cudaFuncSetAttribute(hgemm<EPI_GELU>, cudaFuncAttributeMaxDynamicSharedMemorySize, DSM_G);
    cudaFuncSetAttribute(hgemm<EPI_ADD>,  cudaFuncAttributeMaxDynamicSharedMemorySize, DSM_G);
    cudaFuncSetAttribute(hgemm<EPI_ADDP>, cudaFuncAttributeMaxDynamicSharedMemorySize, DSM_G);
    cudaFuncSetAttribute(hgemm_qkv,       cudaFuncAttributeMaxDynamicSharedMemorySize, DSM_G);

    // weight prep (single fused launch)
    wconv_all<<<3072, dim3(32, 8)>>>(Wq, Wk, Wv, Wo, W1, W2, wtqkv, wto, wt1, wt2);

    // embed (+layer-0 pos) + cls rows, single launch (grid +1 block for cls)
    embed_warp_kernel<<<(Bq * Nn) / 8 + 1, 256>>>(x, W_emb, b_emb, g_emb, be_emb,
                                                  cls_tok, pos, h);

    const int M = Mrows;
    const int mt = (M + HBM - 1) / HBM;               // 65
    const int lnGrid = (M + 7) / 8;                   // 1025
    dim3 gQKV(Ee / HBN, mt, 3);                       // (2, 65, 3)
    dim3 g256(Ee / HBN, mt);                          // (2, 65)
    dim3 g1024(XE / HBN, mt);                         // (8, 65)
    dim3 fgrid((Tt + 127) / 128, Bq * Hh);            // (9, 64)

    for (int l = 0; l < Ll; ++l) {
        // h already carries this layer's pos (embed for l=0, W2 epilogue otherwise)
        ln_warp_kernel<<<lnGrid, 256>>>(h, ln1_g + l * Ee, ln1_b + l * Ee, yh);

        hgemm_qkv<<<gQKV, 256, DSM_G>>>(yh, wtqkv + (size_t)l * Ee * Ee,
                                        bq + l * Ee, bk + l * Ee, bv + l * Ee, qh, kh, vh);

        flash5_kernel<<<fgrid, 256>>>(qh, kh, vh, yh);

        hgemm<EPI_ADD><<<g256, 256, DSM_G>>>(yh, wto + (size_t)l * Ee * Ee,
                                             bo + l * Ee, h, nullptr, h, nullptr, Ee, Ee);

        ln_warp_kernel<<<lnGrid, 256>>>(h, ln2_g + l * Ee, ln2_b + l * Ee, yh);

        hgemm<EPI_GELU><<<g1024, 256, DSM_G>>>(yh, wt1 + (size_t)l * XE * Ee,
                                               b1 + l * XE, nullptr, nullptr,
                                               nullptr, mh, XE, Ee);

        if (l + 1 < Ll) {
            hgemm<EPI_ADDP><<<g256, 256, DSM_G>>>(mh, wt2 + (size_t)l * Ee * XE,
                                                  b2 + l * Ee, h, pos, h, nullptr, Ee, XE);
        } else {
            hgemm<EPI_ADD><<<g256, 256, DSM_G>>>(mh, wt2 + (size_t)l * Ee * XE,
                                                 b2 + l * Ee, h, nullptr, h, nullptr, Ee, XE);
        }
    }

    dim3 pgrid(4, Bq);
    pool_partial_kernel<<<pgrid, 256>>>(h, pp);
    classifier_kernel<<<Bq, 256>>>(pp, Wc1, bc1, lnc_g, lnc_b, Wc2, bc2, (float*)d_out);
}